// round 12
// baseline (speedup 1.0000x reference)
#include <cuda_runtime.h>

#define DIM 2048
#define THETA 1e-18
#define REGEPS 1e-15

// first 50 primes (max 229)
__constant__ int c_primes[50] = {
    2,3,5,7,11,13,17,19,23,29,31,37,41,43,47,53,59,61,67,71,
    73,79,83,89,97,101,103,107,109,113,127,131,137,139,149,151,157,163,167,173,
    179,181,191,193,197,199,211,223,227,229};

#define ROWS_PER_CTA 8
#define HALO 8
#define TBL 24   // band needs indices [base-6, base+13] ⊂ [base-8, base+16)

// Barrier-free split: warps 3..7 zero all non-band float4s (disjoint from band
// windows, no sync needed); warps 0..2 build tables, named-bar among themselves,
// then warp 0 writes the 4-float4 band window of each row (values + edge zeros).
__global__ void __launch_bounds__(256, 2)
fused_kernel(const float* __restrict__ s_real,
             const float* __restrict__ s_imag,
             float* __restrict__ out) {
    __shared__ double sO[TBL];   // Arnold off-1 (indexed by min index)
    __shared__ double sD[TBL];   // Re(n^{-s}) + prime diag corr
    __shared__ double sE[TBL];   // |s|*theta^2*exp(-0.01*m)

    const int base = blockIdx.x * ROWS_PER_CTA;
    const int t = threadIdx.x;
    const float PIf = 3.14159265358979323846f;

    if (t < 96) {
        // ---- tables via fp32 MUFU transcendentals (3 warps, 24 lanes live) ----
        int fam = t >> 5;
        int lm  = t & 31;
        if (lm < TBL) {
            int m  = base - HALO + lm;
            bool ok = (m >= 0 && m < DIM);
            float srf = __ldg(s_real);
            float sif = __ldg(s_imag);
            if (fam == 0) {
                sO[lm] = (ok && m < DIM - 1)
                           ? (double)(THETA) * (double)sinf(PIf * (2.0f * (float)m + 1.0f) / (float)DIM)
                           : 0.0;
            } else if (fam == 1) {
                double dv = 0.0;
                if (ok) {
                    int n = m + 1;
                    float ln_n = logf((float)n);
                    bool isp = false;
                    #pragma unroll
                    for (int p = 0; p < 50; p++) isp |= (c_primes[p] == n);
                    float mag = expf(-srf * ln_n);   // Re(n^{-s}) = e^{-sr ln n} cos(si ln n)
                    float ph  = cosf(sif * ln_n);
                    dv = (double)mag * (double)ph;
                    if (isp) dv += THETA * (double)ln_n * 1.6449340668482264; // zeta(2)
                }
                sD[lm] = dv;
            } else {
                double ev = 0.0;
                if (ok) {
                    float abss = sqrtf(srf * srf + sif * sif);
                    ev = (double)abss * (THETA * THETA) * (double)expf(-0.01f * (float)m);
                }
                sE[lm] = ev;
            }
        }
        // named barrier among the 3 table warps only
        asm volatile("bar.sync 1, 96;" ::: "memory");

        // ---- warp 0: band windows — 8 rows x 4 float4 vectors ----
        if (t < 32) {
            int r  = t >> 2;          // 0..7
            int vi = t & 3;           // 0..3
            int i  = base + r;
            int ws = ((i > 4) ? (i - 4) : 0) >> 2;   // first window vector
            int v  = ws + vi;
            if (v < DIM / 4) {
                auto aval = [&](int x, int y) -> double {
                    // x,y guaranteed in-range for band elems; y checked by caller band mask
                    int dd = x - y; dd = dd < 0 ? -dd : dd;
                    if (dd == 0) return 1.0;  // 1 + theta*cos == 1.0 exactly (f64 too)
                    if (dd == 1) return sO[(x < y ? x : y) - base + HALO];
                    return THETA * THETA * 0.8187307530779818586699355086383;
                };
                float4 o;
                float* e = &o.x;
                #pragma unroll
                for (int c = 0; c < 4; c++) {
                    int j = 4 * v + c;
                    int d = i - j;
                    double sre = 0.0;
                    if (d <= 4 && d >= -4) {
                        #pragma unroll
                        for (int kk = -2; kk <= 2; kk++) {
                            int k = i + kk;
                            if (k < 0 || k >= DIM) continue;
                            int dj = j - k; dj = dj < 0 ? -dj : dj;
                            if (dj > 2) continue;
                            sre += aval(i, k) * sD[k - base + HALO] * aval(j, k);
                        }
                        if (d == 0)                 sre += REGEPS;
                        else if (d == 2 || d == -2) sre += sE[((i < j) ? i : j) - base + HALO];
                    }
                    e[c] = (float)sre;
                }
                ((float4*)out)[(size_t)i * (DIM / 4) + v] = o;
            }
        }
    } else {
        // ---- warps 3..7 (160 threads): zero all non-window float4s, no sync ----
        float4* o4 = (float4*)(out + (size_t)base * DIM);
        const float4 z = make_float4(0.f, 0.f, 0.f, 0.f);
        int tt = t - 96;
        #pragma unroll 4
        for (int v = tt; v < ROWS_PER_CTA * (DIM / 4); v += 160) {
            int r  = v >> 9;           // row within slab
            int cv = v & (DIM / 4 - 1);
            int i  = base + r;
            int ws = ((i > 4) ? (i - 4) : 0) >> 2;
            if ((unsigned)(cv - ws) < 4u) continue;   // band window: owned by warp 0
            o4[v] = z;
        }
    }
}

// ---------------- fallback path (unexpected out_size; fp64 reference math) ----
__device__ double g_aDiag[DIM];
__device__ double g_aOff1[DIM];
__device__ double g_dDiag[DIM];
__device__ double g_exp2[DIM];

__global__ void precompute_kernel(const float* __restrict__ s_real,
                                  const float* __restrict__ s_imag) {
    int m = blockIdx.x * blockDim.x + threadIdx.x;
    if (m >= DIM) return;
    const double PI = 3.141592653589793238462643383279502884;
    double sr = (double)s_real[0], si = (double)s_imag[0];
    g_aDiag[m] = 1.0 + THETA * cos(2.0 * PI * (double)m / (double)DIM);
    g_aOff1[m] = (m < DIM - 1) ? THETA * sin(PI * (2.0 * (double)m + 1.0) / (double)DIM) : 0.0;
    int n = m + 1;
    double ln_n = log((double)n);
    bool isp = false;
    #pragma unroll
    for (int p = 0; p < 50; p++) isp |= (c_primes[p] == n);
    double dv = exp(-sr * ln_n) * cos(si * ln_n);
    if (isp) dv += THETA * ln_n * (PI * PI / 6.0);
    g_dDiag[m] = dv;
    g_exp2[m] = sqrt(sr * sr + si * si) * THETA * THETA * exp(-0.01 * (double)m);
}

__device__ __forceinline__ double AvalG(int x, int y) {
    if (y < 0 || y >= DIM) return 0.0;
    int d = x - y; d = d < 0 ? -d : d;
    if (d > 2) return 0.0;
    if (d == 0) return g_aDiag[x];
    if (d == 1) return g_aOff1[x < y ? x : y];
    return THETA * THETA * 0.8187307530779818586699355086383;
}

__global__ void fill_generic_f32(float* __restrict__ out, int n) {
    int idx = blockIdx.x * blockDim.x + threadIdx.x;
    if (idx >= n) return;
    int m = idx & (DIM * DIM - 1);
    int i = m >> 11, j = m & (DIM - 1);
    double sre = 0.0;
    #pragma unroll
    for (int kk = -2; kk <= 2; kk++) {
        int k = i + kk;
        if (k < 0 || k >= DIM) continue;
        sre += AvalG(i, k) * g_dDiag[k] * AvalG(j, k);
    }
    int d = i - j;
    if (d == 0) sre += REGEPS;
    else if (d == 2 || d == -2) sre += g_exp2[(i < j) ? i : j];
    out[idx] = (float)sre;
}

extern "C" void kernel_launch(void* const* d_in, const int* in_sizes, int n_in,
                              void* d_out, int out_size) {
    const float* s_real = (const float*)d_in[0];
    const float* s_imag = (const float*)((n_in >= 2) ? d_in[1] : d_in[0]);

    const int NTOT = DIM * DIM;
    if (out_size == NTOT) {
        fused_kernel<<<DIM / ROWS_PER_CTA, 256>>>(s_real, s_imag, (float*)d_out);
    } else {
        precompute_kernel<<<(DIM + 255) / 256, 256>>>(s_real, s_imag);
        fill_generic_f32<<<(out_size + 255) / 256, 256>>>((float*)d_out, out_size);
    }
}